// round 15
// baseline (speedup 1.0000x reference)
#include <cuda_runtime.h>
#include <cuda_fp16.h>
#include <cstdint>

// Problem constants
// B=4, S=2048, H=16, dh=64, D=1024, M = B*S = 8192
// Inputs: 0 Q_emb f32  1 K_emb f32  2 V_emb f32  3 Q_ini i32 (unused)
//         4 K_ini i32  5 WQ  6 WK  7 WV  8 WO (all f32 [1024,1024])
// Output: f32 [B,S,D]
//
// compute_103 virtual arch: no tcgen05. Tensor path: cp.async + ldmatrix +
// mma.sync.m16n8k16.f16 (layout validated R10-R14), single-pass fp16.
// Measured model: legacy HMMA rt_SMSP ~= 16 cyc -> mma-issue-bound; this
// round trims non-mma overhead (attn occupancy 2, fp16 V path, ex2 direct).

#define BB   4
#define SS   2048
#define HH   16
#define DH   64
#define DM   1024
#define MM   (BB*SS)          // 8192
#define LOG2E 1.44269504f
#define NEG_BIG2 1.44269504e10f   // 1e10 * log2e (log2-domain mask offset)

// ---------------- scratch (device globals; no allocations allowed) --------
__device__ float  g_vmean[BB*HH*DH];      // [BH,dh]
__device__ __half g_qh [BB*HH*SS*DH];     // Q fp16 (unscaled), [bh][s][dh]
__device__ __half g_kh [BB*HH*SS*DH];     // K fp16, [bh][s][dh]
__device__ __half g_vh [BB*HH*SS*DH];     // V fp16, [bh][s][dh]
__device__ __half g_vth[BB*HH*SS*DH];     // V^T fp16, [bh][dh][s]
__device__ __half g_x[3][MM*DM];          // X fp16: slots 0/1/2 = Q/K/V emb
                                          //  (slot 0 reused for ctx -> WO)
__device__ __half g_wt4[4][DM*DM];        // W^T fp16 [N][K]: WQ,WK,WV,WO

// ======================= inline PTX helpers (compute_103-safe) ============
__device__ __forceinline__ uint32_t smem_u32(const void* p) {
    uint32_t a;
    asm("{ .reg .u64 t; cvta.to.shared.u64 t, %1; cvt.u32.u64 %0, t; }"
        : "=r"(a) : "l"(p));
    return a;
}
__device__ __forceinline__ void cp_async16(uint32_t dst, const void* src) {
    asm volatile("cp.async.cg.shared.global [%0], [%1], 16;"
                 :: "r"(dst), "l"(src) : "memory");
}
#define CP_COMMIT()  asm volatile("cp.async.commit_group;" ::: "memory")
#define CP_WAIT(n)   asm volatile("cp.async.wait_group %0;" :: "n"(n) : "memory")

__device__ __forceinline__ void ldsm_x4(uint32_t r[4], uint32_t addr) {
    asm volatile("ldmatrix.sync.aligned.m8n8.x4.shared.b16 {%0,%1,%2,%3}, [%4];"
                 : "=r"(r[0]), "=r"(r[1]), "=r"(r[2]), "=r"(r[3]) : "r"(addr));
}
__device__ __forceinline__ void mma16816(float c[4], const uint32_t a[4],
                                         uint32_t b0, uint32_t b1) {
    asm volatile(
        "mma.sync.aligned.m16n8k16.row.col.f32.f16.f16.f32 "
        "{%0,%1,%2,%3}, {%4,%5,%6,%7}, {%8,%9}, {%0,%1,%2,%3};"
        : "+f"(c[0]), "+f"(c[1]), "+f"(c[2]), "+f"(c[3])
        : "r"(a[0]), "r"(a[1]), "r"(a[2]), "r"(a[3]), "r"(b0), "r"(b1));
}
__device__ __forceinline__ uint32_t pk2(__half lo, __half hi) {
    __half2 v(lo, hi);
    return *(uint32_t*)&v;
}
__device__ __forceinline__ float ex2(float x) {
    float y;
    asm("ex2.approx.ftz.f32 %0, %1;" : "=f"(y) : "f"(x));
    return y;
}

// ======================= fused conversion kernels =========================
// grid (8192, 3): y selects Q/K/V embedding -> g_x[y] (single fp16)
__global__ void conv_x_kernel(const float* __restrict__ q,
                              const float* __restrict__ k,
                              const float* __restrict__ v)
{
    const int z = blockIdx.y;
    const float* X = (z == 0) ? q : (z == 1) ? k : v;
    __half* dh = g_x[z];
    const size_t idx = (size_t)blockIdx.x * blockDim.x + threadIdx.x; // float4
    float4 vv = ((const float4*)X)[idx];
    ((__half2*)dh)[idx*2+0] = __half2(__float2half_rn(vv.x), __float2half_rn(vv.y));
    ((__half2*)dh)[idx*2+1] = __half2(__float2half_rn(vv.z), __float2half_rn(vv.w));
}

// grid (1024, 4): y selects WQ/WK/WV/WO; W f32 [K,N] -> W^T fp16 [N,K]
__global__ void conv_w_kernel(const float* __restrict__ wq,
                              const float* __restrict__ wk,
                              const float* __restrict__ wv,
                              const float* __restrict__ wo)
{
    const int z = blockIdx.y;
    const float* W = (z == 0) ? wq : (z == 1) ? wk : (z == 2) ? wv : wo;
    __half* dst = g_wt4[z];
    const int idx = blockIdx.x * blockDim.x + threadIdx.x;
    const int n  = idx >> 8;
    const int kq = (idx & 255) << 2;
    __half h[4];
    #pragma unroll
    for (int j = 0; j < 4; ++j)
        h[j] = __float2half_rn(W[(size_t)(kq + j) * DM + n]);
    const size_t o2 = ((size_t)n * DM + kq) >> 1;
    ((__half2*)dst)[o2+0] = __half2(h[0], h[1]);
    ((__half2*)dst)[o2+1] = __half2(h[2], h[3]);
}

// ============== HMMA GEMM: C[8192,1024] = X @ W (fp16 1-pass) =============
// 128x128 CTA tile, K-chunks of 32, cp.async double-buffered SMEM.
// 8 warps = 2(M) x 4(N); warp tile 64x32 = 4x4 m16n8k16 fragments.
// blockIdx.z selects (X slot, W slot, dst) = (xsel+z, wsel+z, dsel+z).
#define MAT_BYTES (128*80)            // 10240 B
#define BUFB      (2*MAT_BYTES)       // X, Wt = 20480 B
#define GEMM_SMEM (2*BUFB)            // 40960 B

__global__ __launch_bounds__(256, 2)
void mma_gemm_kernel(float* __restrict__ Yplain, int xsel, int wsel, int dsel)
{
    extern __shared__ char smg[];
    const int tid  = threadIdx.x;
    const int lane = tid & 31;
    const int wid  = tid >> 5;
    const int wm   = wid >> 2;
    const int wn   = wid & 3;
    const int bm   = blockIdx.y * 128;
    const int bn   = blockIdx.x * 128;
    const uint32_t sbase = smem_u32(smg);

    const int z = blockIdx.z;
    const __half* Xh = g_x  [xsel + z];
    const __half* Wt = g_wt4[wsel + z];
    const int dst_sel = dsel + z;

    float acc[4][4][4];
    #pragma unroll
    for (int i = 0; i < 4; ++i)
        #pragma unroll
        for (int j = 0; j < 4; ++j)
            #pragma unroll
            for (int t = 0; t < 4; ++t) acc[i][j][t] = 0.f;

    auto load_chunk = [&](int kc, int b) {
        const uint32_t base = sbase + b*BUFB;
        #pragma unroll
        for (int t = 0; t < 2; ++t) {
            const int idx = tid + (t << 8);
            const int r = idx >> 2, c = idx & 3;
            const uint32_t so = (uint32_t)(r*80 + c*16);
            const size_t ea = (size_t)(bm + r)*DM + kc*32 + c*8;
            const size_t eb = (size_t)(bn + r)*DM + kc*32 + c*8;
            cp_async16(base +             so, Xh + ea);
            cp_async16(base + MAT_BYTES + so, Wt + eb);
        }
        CP_COMMIT();
    };

    load_chunk(0, 0);

    for (int kc = 0; kc < 32; ++kc) {
        const int b = kc & 1;
        if (kc < 31) { load_chunk(kc + 1, b ^ 1); CP_WAIT(1); }
        else         { CP_WAIT(0); }
        __syncthreads();

        const uint32_t abase = sbase + b*BUFB;
        const uint32_t bbase = abase + MAT_BYTES;

        #pragma unroll
        for (int ks = 0; ks < 2; ++ks) {
            const uint32_t colB = (uint32_t)(ks*32 + (lane >> 4)*16);

            uint32_t af[4][4];
            #pragma unroll
            for (int i = 0; i < 4; ++i) {
                const uint32_t ad = abase +
                    (uint32_t)((wm*64 + i*16 + (lane & 15))*80) + colB;
                ldsm_x4(af[i], ad);
            }
            uint32_t bq[4][2];
            #pragma unroll
            for (int jp = 0; jp < 2; ++jp) {
                uint32_t r4[4];
                const uint32_t bd = bbase +
                    (uint32_t)((wn*32 + jp*16 + (lane & 15))*80) + colB;
                ldsm_x4(r4, bd);
                bq[2*jp+0][0] = r4[0]; bq[2*jp+0][1] = r4[2];
                bq[2*jp+1][0] = r4[1]; bq[2*jp+1][1] = r4[3];
            }
            #pragma unroll
            for (int i = 0; i < 4; ++i)
                #pragma unroll
                for (int j = 0; j < 4; ++j)
                    mma16816(acc[i][j], af[i], bq[j][0], bq[j][1]);
        }
        __syncthreads();
    }

    // ---- epilogue: 0=Q fp16, 1=K fp16, 2=V fp16, 3=plain fp32
    const int tg = lane >> 2;
    const int t4 = lane & 3;
    #pragma unroll
    for (int i = 0; i < 4; ++i) {
        #pragma unroll
        for (int j = 0; j < 4; ++j) {
            const int m0 = bm + wm*64 + i*16 + tg;
            const int n0 = bn + wn*32 + j*8 + t4*2;
            #pragma unroll
            for (int half = 0; half < 2; ++half) {
                const int m = m0 + half*8;
                const float x = acc[i][j][half*2+0];
                const float y = acc[i][j][half*2+1];
                if (dst_sel <= 2) {
                    const int bb = m >> 11, s = m & (SS-1);
                    const int h  = n0 >> 6, d = n0 & (DH-1);
                    const size_t oi = ((size_t)((bb << 4) + h) * SS + s) * DH + d;
                    __half* Y = (dst_sel == 0) ? g_qh
                              : (dst_sel == 1) ? g_kh : g_vh;
                    *(__half2*)&Y[oi] =
                        __half2(__float2half_rn(x), __float2half_rn(y));
                } else {
                    *(float2*)&Yplain[(size_t)m * DM + n0] = make_float2(x, y);
                }
            }
        }
    }
}

// =============== V^T: g_vh [bh][s][dh] -> g_vth [bh][dh][s] (fp16) ========
__global__ void vt_split_kernel()
{
    __shared__ __half t[64][66];   // stride 66 halves: write-conflict-free
    const int bh = blockIdx.y;
    const int sb = blockIdx.x << 6;
    const int tid = threadIdx.x;
    {
        const int s = tid >> 2, g = (tid & 3) << 4;
        const __half2* src = (const __half2*)&g_vh[((size_t)bh*SS + sb + s)*DH + g];
        #pragma unroll
        for (int j = 0; j < 8; ++j)
            *(__half2*)&t[s][g + 2*j] = src[j];
    }
    __syncthreads();
    const int d  = tid & 63;
    const int s0 = (tid >> 6) << 4;
    #pragma unroll
    for (int j = 0; j < 16; j += 2) {
        const size_t oi = ((size_t)bh*DH + d)*SS + sb + s0 + j;
        *(__half2*)&g_vth[oi] = __half2(t[s0+j][d], t[s0+j+1][d]);
    }
}

// =================== vmean: mean over S of V per (bh, d) ==================
__global__ void vmean_kernel()
{
    __shared__ float red[512];
    const int bh = blockIdx.x;
    const int d  = threadIdx.x & 63;
    const int sc = threadIdx.x >> 6;
    float acc = 0.f;
    const int base = (bh << 11) + (sc << 8);
    #pragma unroll 8
    for (int s = 0; s < 256; ++s)
        acc += __half2float(g_vh[(size_t)(base + s) * DH + d]);
    red[threadIdx.x] = acc;
    __syncthreads();
    if (sc == 0) {
        float t = 0.f;
        #pragma unroll
        for (int j = 0; j < 8; ++j) t += red[(j << 6) + d];
        g_vmean[(bh << 6) + d] = t * (1.0f/2048.0f);
    }
}

// =================== HMMA flash attention (fp16, log2-domain) =============
// CTA = (bh, q-tile of 128 rows), 256 threads = 8 warps; warp w owns rows
// w*16..w*16+15. Q fp16 resident; K/V fp16, 64-key tiles, double-buffered.
// Scores kept in log2 domain: scale = 0.125*log2e folded pre-mask, masked
// entries absorb to exactly -1.4427e10, exp via ex2.approx.
#define ATT_ROWB  144                 // smem row stride (128 B + 16 pad)
#define ATT_KMATB (64*ATT_ROWB)       // 9216  (K or V^T tile)
#define ATT_QMATB (128*ATT_ROWB)      // 18432 (Q tile)
#define ATT_KV(b) (ATT_QMATB + (b)*2*ATT_KMATB)
#define ATT_KINI  (ATT_QMATB + 4*ATT_KMATB)     // 55296
#define ATT_SMEM  (ATT_KINI + 512)              // 55808

__global__ __launch_bounds__(256, 2)
void attn_kernel(const int* __restrict__ K_ini)
{
    extern __shared__ char attsm[];
    const uint32_t sb = smem_u32(attsm);
    const int tid  = threadIdx.x;
    const int lane = tid & 31;
    const int w    = tid >> 5;                 // 0..7
    const int qt   = (SS/128 - 1) - blockIdx.x; // longest CTAs first
    const int bh   = blockIdx.y;
    const int b    = bh >> 4;
    const int h    = bh & 15;

    const size_t qkbase = (size_t)bh * SS * DH;   // [bh][s][dh]
    const size_t vtbase = (size_t)bh * DH * SS;   // [bh][dh][s]

    auto load_kv = [&](int kt, int bf) {
        const uint32_t kb = sb + ATT_KV(bf);
        #pragma unroll
        for (int i = 0; i < 2; ++i) {
            const int f = tid + (i << 8);
            const int r = f >> 3, c = f & 7;     // r 0..63
            const uint32_t so = (uint32_t)(r*ATT_ROWB + c*16);
            const size_t gk = qkbase + (size_t)(kt*64 + r)*DH + c*8;
            const size_t gv = vtbase + (size_t)r*SS + kt*64 + c*8;
            cp_async16(kb +             so, g_kh  + gk);
            cp_async16(kb + ATT_KMATB + so, g_vth + gv);
        }
        CP_COMMIT();
    };

    // ---- prologue: Q (128 rows) + K/V tile 0 + kini0
    #pragma unroll
    for (int i = 0; i < 4; ++i) {
        const int f = tid + (i << 8);
        const int r = f >> 3, c = f & 7;         // r 0..127
        const uint32_t so = (uint32_t)(r*ATT_ROWB + c*16);
        const size_t gq = qkbase + (size_t)(qt*128 + r)*DH + c*8;
        cp_async16(sb + so, g_qh + gq);
    }
    load_kv(0, 0);
    if (tid < 16)
        ((int4*)(attsm + ATT_KINI))[tid] = ((const int4*)(K_ini + b*SS))[tid];
    CP_WAIT(0);
    __syncthreads();

    // ---- Q A-fragments (resident)
    uint32_t qf[4][4];
    const uint32_t lrow16 = (uint32_t)((lane & 15) * ATT_ROWB);
    const uint32_t lcol   = (uint32_t)((lane >> 4) << 4);
    #pragma unroll
    for (int kd = 0; kd < 4; ++kd) {
        const uint32_t qa = sb + (uint32_t)(w*16*ATT_ROWB) + lrow16 + kd*32 + lcol;
        ldsm_x4(qf[kd], qa);
    }

    float o[8][4];
    #pragma unroll
    for (int jd = 0; jd < 8; ++jd)
        #pragma unroll
        for (int e = 0; e < 4; ++e) o[jd][e] = 0.f;
    float mrow[2] = {-3.0e38f, -3.0e38f};   // log2-domain running max
    float lrow[2] = {0.f, 0.f};

    const int qr_loc = w*16 + (lane >> 2);     // tile-local row (half0), 0..127
    const int ktmax  = 2*qt + 1;

    for (int kt = 0; kt <= ktmax; ++kt) {
        const int buf = kt & 1;
        if (kt < ktmax) { load_kv(kt + 1, buf ^ 1); CP_WAIT(1); }
        else            { CP_WAIT(0); }
        __syncthreads();
        if (kt < ktmax && tid < 16)
            ((int4*)(attsm + ATT_KINI))[(buf ^ 1)*16 + tid] =
                ((const int4*)(K_ini + b*SS + (kt + 1)*64))[tid];

        // ---- scores S = Q.K^T (1-pass fp16)
        float s[8][4];
        #pragma unroll
        for (int jn = 0; jn < 8; ++jn)
            #pragma unroll
            for (int e = 0; e < 4; ++e) s[jn][e] = 0.f;

        const uint32_t kb = sb + ATT_KV(buf);
        #pragma unroll
        for (int nk = 0; nk < 4; ++nk) {
            #pragma unroll
            for (int kd = 0; kd < 4; ++kd) {
                uint32_t kf[4];
                const uint32_t ad = kb + (uint32_t)(nk*16*ATT_ROWB) + lrow16
                                  + kd*32 + lcol;
                ldsm_x4(kf, ad);
                mma16816(s[nk*2+0], qf[kd], kf[0], kf[2]);
                mma16816(s[nk*2+1], qf[kd], kf[1], kf[3]);
            }
        }

        // ---- scale to log2 domain, mask, tile max
        const int* kini = (const int*)(attsm + ATT_KINI) + buf*64;
        const int needc = (kt >= 2*qt);
        float tmax[2] = {-3.0e38f, -3.0e38f};
        #pragma unroll
        for (int jn = 0; jn < 8; ++jn) {
            #pragma unroll
            for (int e = 0; e < 4; ++e) {
                const int col  = jn*8 + ((lane & 3) << 1) + (e & 1);
                const int half = e >> 1;
                bool masked = (kini[col] == 0);
                if (needc) masked = masked || (kt*64 + col > qt*128 + qr_loc + half*8);
                float sv = s[jn][e] * (0.125f * LOG2E);
                if (masked) sv -= NEG_BIG2;      // exact -1.4427e10 (absorb)
                s[jn][e] = sv;
                tmax[half] = fmaxf(tmax[half], sv);
            }
        }
        #pragma unroll
        for (int half = 0; half < 2; ++half) {
            tmax[half] = fmaxf(tmax[half], __shfl_xor_sync(0xffffffffu, tmax[half], 1));
            tmax[half] = fmaxf(tmax[half], __shfl_xor_sync(0xffffffffu, tmax[half], 2));
        }
        const float nm0 = fmaxf(mrow[0], tmax[0]);
        const float nm1 = fmaxf(mrow[1], tmax[1]);
        const float sc0 = ex2(mrow[0] - nm0);
        const float sc1 = ex2(mrow[1] - nm1);
        mrow[0] = nm0; mrow[1] = nm1;

        // ---- exp2 + P into A-frags (register-only, single fp16)
        uint32_t ap[4][4];
        float ls0 = 0.f, ls1 = 0.f;
        #pragma unroll
        for (int jn = 0; jn < 8; ++jn) {
            const float p0 = ex2(s[jn][0] - nm0);
            const float p1 = ex2(s[jn][1] - nm0);
            const float p2 = ex2(s[jn][2] - nm1);
            const float p3 = ex2(s[jn][3] - nm1);
            ls0 += p0 + p1; ls1 += p2 + p3;
            const int kp  = jn >> 1;
            const int sub = (jn & 1) << 1;
            ap[kp][sub+0] = pk2(__float2half_rn(p0), __float2half_rn(p1));
            ap[kp][sub+1] = pk2(__float2half_rn(p2), __float2half_rn(p3));
        }
        ls0 += __shfl_xor_sync(0xffffffffu, ls0, 1);
        ls0 += __shfl_xor_sync(0xffffffffu, ls0, 2);
        ls1 += __shfl_xor_sync(0xffffffffu, ls1, 1);
        ls1 += __shfl_xor_sync(0xffffffffu, ls1, 2);
        lrow[0] = lrow[0]*sc0 + ls0;
        lrow[1] = lrow[1]*sc1 + ls1;
        #pragma unroll
        for (int jd = 0; jd < 8; ++jd) {
            o[jd][0] *= sc0; o[jd][1] *= sc0;
            o[jd][2] *= sc1; o[jd][3] *= sc1;
        }

        // ---- O += P.V (1-pass fp16)
        const uint32_t vb = kb + ATT_KMATB;
        #pragma unroll
        for (int nd = 0; nd < 4; ++nd) {
            #pragma unroll
            for (int kp = 0; kp < 4; ++kp) {
                uint32_t vf[4];
                const uint32_t ad = vb + (uint32_t)(nd*16*ATT_ROWB) + lrow16
                                  + kp*32 + lcol;
                ldsm_x4(vf, ad);
                mma16816(o[nd*2+0], ap[kp], vf[0], vf[2]);
                mma16816(o[nd*2+1], ap[kp], vf[1], vf[3]);
            }
        }
        __syncthreads();   // protect buf reuse by next iteration's prefetch
    }

    // ---- epilogue: ctx fp16 into the WO-GEMM input (slot 0)
    #pragma unroll
    for (int half = 0; half < 2; ++half) {
        const int row = qr_loc + half*8;
        const size_t mg = (size_t)(b*SS + qt*128 + row);
        const float inv = 1.0f / lrow[half];
        const bool fullmask = (mrow[half] < -1e9f);
        #pragma unroll
        for (int jd = 0; jd < 8; ++jd) {
            const int d = jd*8 + ((lane & 3) << 1);
            float v0, v1;
            if (fullmask) {
                // reference: all scores exactly -1e10 -> uniform softmax over
                // ALL 2048 keys -> mean of V
                v0 = g_vmean[bh*64 + d];
                v1 = g_vmean[bh*64 + d + 1];
            } else {
                v0 = o[jd][half*2+0] * inv;
                v1 = o[jd][half*2+1] * inv;
            }
            const size_t oi = mg*DM + h*64 + d;
            *(__half2*)&g_x[0][oi] =
                __half2(__float2half_rn(v0), __float2half_rn(v1));
        }
    }
}

// ============================ launch ======================================
extern "C" void kernel_launch(void* const* d_in, const int* in_sizes, int n_in,
                              void* d_out, int out_size)
{
    const float* Q_emb = (const float*)d_in[0];
    const float* K_emb = (const float*)d_in[1];
    const float* V_emb = (const float*)d_in[2];
    const int*   K_ini = (const int*)  d_in[4];
    const float* WQ    = (const float*)d_in[5];
    const float* WK    = (const float*)d_in[6];
    const float* WV    = (const float*)d_in[7];
    const float* WO    = (const float*)d_in[8];
    float* out = (float*)d_out;
    (void)in_sizes; (void)n_in; (void)out_size;

    cudaFuncSetAttribute(mma_gemm_kernel,
                         cudaFuncAttributeMaxDynamicSharedMemorySize, GEMM_SMEM);
    cudaFuncSetAttribute(attn_kernel,
                         cudaFuncAttributeMaxDynamicSharedMemorySize, ATT_SMEM);

    // fused conversions (one launch each)
    conv_w_kernel<<<dim3((DM*256)/256, 4), 256>>>(WQ, WK, WV, WO);
    conv_x_kernel<<<dim3((MM*DM/4)/256, 3), 256>>>(Q_emb, K_emb, V_emb);

    // fused QKV projections: grid.z = 3 -> (X_z, W_z, dst_z)
    mma_gemm_kernel<<<dim3(DM/128, MM/128, 3), 256, GEMM_SMEM>>>(nullptr, 0, 0, 0);

    vt_split_kernel<<<dim3(SS/64, BB*HH), 256>>>();   // -> V^T fp16
    vmean_kernel<<<BB*HH, 512>>>();

    attn_kernel<<<dim3(SS/128, BB*HH), 256, ATT_SMEM>>>(K_ini); // -> ctx fp16

    // output projection: ctx (slot 0) @ WO -> out
    mma_gemm_kernel<<<dim3(DM/128, MM/128, 1), 256, GEMM_SMEM>>>(out, 0, 3, 3);
}

// round 16
// speedup vs baseline: 1.4413x; 1.4413x over previous
#include <cuda_runtime.h>
#include <cuda_fp16.h>
#include <cstdint>

// Problem constants
// B=4, S=2048, H=16, dh=64, D=1024, M = B*S = 8192
// Inputs: 0 Q_emb f32  1 K_emb f32  2 V_emb f32  3 Q_ini i32 (unused)
//         4 K_ini i32  5 WQ  6 WK  7 WV  8 WO (all f32 [1024,1024])
// Output: f32 [B,S,D]
//
// compute_103 virtual arch: no tcgen05. Tensor path: cp.async + ldmatrix +
// mma.sync.m16n8k16.f16 (layout validated R10-R14), single-pass fp16.
// R16 = R14 (best: 559us) + log2-domain softmax only. R15's occupancy-2
// attn (register spills) and fp16 vt_split (scalar LDS) are reverted.

#define BB   4
#define SS   2048
#define HH   16
#define DH   64
#define DM   1024
#define MM   (BB*SS)          // 8192
#define LOG2E 1.44269504f
#define NEG_BIG2 1.44269504e10f   // 1e10 * log2e (log2-domain mask offset)

// ---------------- scratch (device globals; no allocations allowed) --------
__device__ float  g_v[BB*HH*SS*DH];       // [BH,S,dh] fp32
__device__ float  g_vmean[BB*HH*DH];      // [BH,dh]
__device__ __half g_qh [BB*HH*SS*DH];     // Q fp16 (unscaled), [bh][s][dh]
__device__ __half g_kh [BB*HH*SS*DH];     // K fp16, [bh][s][dh]
__device__ __half g_vth[BB*HH*SS*DH];     // V^T fp16, [bh][dh][s]
__device__ __half g_x[3][MM*DM];          // X fp16: slots 0/1/2 = Q/K/V emb
                                          //  (slot 0 reused for ctx -> WO)
__device__ __half g_wt4[4][DM*DM];        // W^T fp16 [N][K]: WQ,WK,WV,WO

// ======================= inline PTX helpers (compute_103-safe) ============
__device__ __forceinline__ uint32_t smem_u32(const void* p) {
    uint32_t a;
    asm("{ .reg .u64 t; cvta.to.shared.u64 t, %1; cvt.u32.u64 %0, t; }"
        : "=r"(a) : "l"(p));
    return a;
}
__device__ __forceinline__ void cp_async16(uint32_t dst, const void* src) {
    asm volatile("cp.async.cg.shared.global [%0], [%1], 16;"
                 :: "r"(dst), "l"(src) : "memory");
}
#define CP_COMMIT()  asm volatile("cp.async.commit_group;" ::: "memory")
#define CP_WAIT(n)   asm volatile("cp.async.wait_group %0;" :: "n"(n) : "memory")

__device__ __forceinline__ void ldsm_x4(uint32_t r[4], uint32_t addr) {
    asm volatile("ldmatrix.sync.aligned.m8n8.x4.shared.b16 {%0,%1,%2,%3}, [%4];"
                 : "=r"(r[0]), "=r"(r[1]), "=r"(r[2]), "=r"(r[3]) : "r"(addr));
}
__device__ __forceinline__ void mma16816(float c[4], const uint32_t a[4],
                                         uint32_t b0, uint32_t b1) {
    asm volatile(
        "mma.sync.aligned.m16n8k16.row.col.f32.f16.f16.f32 "
        "{%0,%1,%2,%3}, {%4,%5,%6,%7}, {%8,%9}, {%0,%1,%2,%3};"
        : "+f"(c[0]), "+f"(c[1]), "+f"(c[2]), "+f"(c[3])
        : "r"(a[0]), "r"(a[1]), "r"(a[2]), "r"(a[3]), "r"(b0), "r"(b1));
}
__device__ __forceinline__ uint32_t pk2(__half lo, __half hi) {
    __half2 v(lo, hi);
    return *(uint32_t*)&v;
}
__device__ __forceinline__ float ex2(float x) {
    float y;
    asm("ex2.approx.ftz.f32 %0, %1;" : "=f"(y) : "f"(x));
    return y;
}

// ======================= fused conversion kernels =========================
// grid (8192, 3): y selects Q/K/V embedding -> g_x[y] (single fp16)
__global__ void conv_x_kernel(const float* __restrict__ q,
                              const float* __restrict__ k,
                              const float* __restrict__ v)
{
    const int z = blockIdx.y;
    const float* X = (z == 0) ? q : (z == 1) ? k : v;
    __half* dh = g_x[z];
    const size_t idx = (size_t)blockIdx.x * blockDim.x + threadIdx.x; // float4
    float4 vv = ((const float4*)X)[idx];
    ((__half2*)dh)[idx*2+0] = __half2(__float2half_rn(vv.x), __float2half_rn(vv.y));
    ((__half2*)dh)[idx*2+1] = __half2(__float2half_rn(vv.z), __float2half_rn(vv.w));
}

// grid (1024, 4): y selects WQ/WK/WV/WO; W f32 [K,N] -> W^T fp16 [N,K]
__global__ void conv_w_kernel(const float* __restrict__ wq,
                              const float* __restrict__ wk,
                              const float* __restrict__ wv,
                              const float* __restrict__ wo)
{
    const int z = blockIdx.y;
    const float* W = (z == 0) ? wq : (z == 1) ? wk : (z == 2) ? wv : wo;
    __half* dst = g_wt4[z];
    const int idx = blockIdx.x * blockDim.x + threadIdx.x;
    const int n  = idx >> 8;
    const int kq = (idx & 255) << 2;
    __half h[4];
    #pragma unroll
    for (int j = 0; j < 4; ++j)
        h[j] = __float2half_rn(W[(size_t)(kq + j) * DM + n]);
    const size_t o2 = ((size_t)n * DM + kq) >> 1;
    ((__half2*)dst)[o2+0] = __half2(h[0], h[1]);
    ((__half2*)dst)[o2+1] = __half2(h[2], h[3]);
}

// ============== HMMA GEMM: C[8192,1024] = X @ W (fp16 1-pass) =============
// 128x128 CTA tile, K-chunks of 32, cp.async double-buffered SMEM.
// 8 warps = 2(M) x 4(N); warp tile 64x32 = 4x4 m16n8k16 fragments.
// blockIdx.z selects (X slot, W slot, dst) = (xsel+z, wsel+z, dsel+z).
#define MAT_BYTES (128*80)            // 10240 B
#define BUFB      (2*MAT_BYTES)       // X, Wt = 20480 B
#define GEMM_SMEM (2*BUFB)            // 40960 B

__global__ __launch_bounds__(256, 2)
void mma_gemm_kernel(float* __restrict__ Yplain, int xsel, int wsel, int dsel)
{
    extern __shared__ char smg[];
    const int tid  = threadIdx.x;
    const int lane = tid & 31;
    const int wid  = tid >> 5;
    const int wm   = wid >> 2;
    const int wn   = wid & 3;
    const int bm   = blockIdx.y * 128;
    const int bn   = blockIdx.x * 128;
    const uint32_t sbase = smem_u32(smg);

    const int z = blockIdx.z;
    const __half* Xh = g_x  [xsel + z];
    const __half* Wt = g_wt4[wsel + z];
    const int dst_sel = dsel + z;

    float acc[4][4][4];
    #pragma unroll
    for (int i = 0; i < 4; ++i)
        #pragma unroll
        for (int j = 0; j < 4; ++j)
            #pragma unroll
            for (int t = 0; t < 4; ++t) acc[i][j][t] = 0.f;

    auto load_chunk = [&](int kc, int b) {
        const uint32_t base = sbase + b*BUFB;
        #pragma unroll
        for (int t = 0; t < 2; ++t) {
            const int idx = tid + (t << 8);
            const int r = idx >> 2, c = idx & 3;
            const uint32_t so = (uint32_t)(r*80 + c*16);
            const size_t ea = (size_t)(bm + r)*DM + kc*32 + c*8;
            const size_t eb = (size_t)(bn + r)*DM + kc*32 + c*8;
            cp_async16(base +             so, Xh + ea);
            cp_async16(base + MAT_BYTES + so, Wt + eb);
        }
        CP_COMMIT();
    };

    load_chunk(0, 0);

    for (int kc = 0; kc < 32; ++kc) {
        const int b = kc & 1;
        if (kc < 31) { load_chunk(kc + 1, b ^ 1); CP_WAIT(1); }
        else         { CP_WAIT(0); }
        __syncthreads();

        const uint32_t abase = sbase + b*BUFB;
        const uint32_t bbase = abase + MAT_BYTES;

        #pragma unroll
        for (int ks = 0; ks < 2; ++ks) {
            const uint32_t colB = (uint32_t)(ks*32 + (lane >> 4)*16);

            uint32_t af[4][4];
            #pragma unroll
            for (int i = 0; i < 4; ++i) {
                const uint32_t ad = abase +
                    (uint32_t)((wm*64 + i*16 + (lane & 15))*80) + colB;
                ldsm_x4(af[i], ad);
            }
            uint32_t bq[4][2];
            #pragma unroll
            for (int jp = 0; jp < 2; ++jp) {
                uint32_t r4[4];
                const uint32_t bd = bbase +
                    (uint32_t)((wn*32 + jp*16 + (lane & 15))*80) + colB;
                ldsm_x4(r4, bd);
                bq[2*jp+0][0] = r4[0]; bq[2*jp+0][1] = r4[2];
                bq[2*jp+1][0] = r4[1]; bq[2*jp+1][1] = r4[3];
            }
            #pragma unroll
            for (int i = 0; i < 4; ++i)
                #pragma unroll
                for (int j = 0; j < 4; ++j)
                    mma16816(acc[i][j], af[i], bq[j][0], bq[j][1]);
        }
        __syncthreads();
    }

    // ---- epilogue: 0=Q fp16, 1=K fp16, 2=V fp32, 3=plain fp32
    const int tg = lane >> 2;
    const int t4 = lane & 3;
    #pragma unroll
    for (int i = 0; i < 4; ++i) {
        #pragma unroll
        for (int j = 0; j < 4; ++j) {
            const int m0 = bm + wm*64 + i*16 + tg;
            const int n0 = bn + wn*32 + j*8 + t4*2;
            #pragma unroll
            for (int half = 0; half < 2; ++half) {
                const int m = m0 + half*8;
                const float x = acc[i][j][half*2+0];
                const float y = acc[i][j][half*2+1];
                if (dst_sel <= 1) {
                    const int bb = m >> 11, s = m & (SS-1);
                    const int h  = n0 >> 6, d = n0 & (DH-1);
                    const size_t oi = ((size_t)((bb << 4) + h) * SS + s) * DH + d;
                    __half2 hv(__float2half_rn(x), __float2half_rn(y));
                    if (dst_sel == 0) *(__half2*)&g_qh[oi] = hv;
                    else              *(__half2*)&g_kh[oi] = hv;
                } else if (dst_sel == 2) {
                    const int bb = m >> 11, s = m & (SS-1);
                    const int h  = n0 >> 6, d = n0 & (DH-1);
                    *(float2*)&g_v[((size_t)((bb << 4) + h) * SS + s) * DH + d] =
                        make_float2(x, y);
                } else {
                    *(float2*)&Yplain[(size_t)m * DM + n0] = make_float2(x, y);
                }
            }
        }
    }
}

// =============== V^T transpose + fp16: g_v -> g_vth [bh][dh][s] ===========
__global__ void vt_split_kernel()
{
    __shared__ float t[64][65];
    const int bh = blockIdx.y;
    const int sb = blockIdx.x << 6;
    const int tid = threadIdx.x;
    #pragma unroll
    for (int i = 0; i < 4; ++i) {
        const int f = tid + (i << 8);
        const int s = f >> 4, d4 = (f & 15) << 2;
        float4 v = *(const float4*)&g_v[((size_t)bh*SS + sb + s)*DH + d4];
        t[s][d4+0] = v.x; t[s][d4+1] = v.y; t[s][d4+2] = v.z; t[s][d4+3] = v.w;
    }
    __syncthreads();
    const int d  = tid >> 2;
    const int s0 = (tid & 3) << 4;
    #pragma unroll
    for (int j = 0; j < 16; j += 2) {
        const size_t oi = ((size_t)bh*DH + d)*SS + sb + s0 + j;
        *(__half2*)&g_vth[oi] = __half2(__float2half_rn(t[s0+j][d]),
                                        __float2half_rn(t[s0+j+1][d]));
    }
}

// =================== vmean: mean over S of V per (bh, d) ==================
__global__ void vmean_kernel()
{
    __shared__ float red[512];
    const int bh = blockIdx.x;
    const int d  = threadIdx.x & 63;
    const int sc = threadIdx.x >> 6;
    float acc = 0.f;
    const int base = (bh << 11) + (sc << 8);
    #pragma unroll 8
    for (int s = 0; s < 256; ++s)
        acc += g_v[(size_t)(base + s) * DH + d];
    red[threadIdx.x] = acc;
    __syncthreads();
    if (sc == 0) {
        float t = 0.f;
        #pragma unroll
        for (int j = 0; j < 8; ++j) t += red[(j << 6) + d];
        g_vmean[(bh << 6) + d] = t * (1.0f/2048.0f);
    }
}

// =================== HMMA flash attention (fp16, log2-domain) =============
// CTA = (bh, q-tile of 128 rows), 256 threads = 8 warps; warp w owns rows
// w*16..w*16+15. Q fp16 resident; K/V fp16, 64-key tiles, double-buffered.
// Scores in log2 domain: 0.125*log2e folded pre-mask; masked entries absorb
// to exactly -1.4427e10; exp via ex2.approx. Occupancy 1 (R15 showed
// forcing 2 spills registers).
#define ATT_ROWB  144                 // smem row stride (128 B + 16 pad)
#define ATT_KMATB (64*ATT_ROWB)       // 9216  (K or V^T tile)
#define ATT_QMATB (128*ATT_ROWB)      // 18432 (Q tile)
#define ATT_KV(b) (ATT_QMATB + (b)*2*ATT_KMATB)
#define ATT_KINI  (ATT_QMATB + 4*ATT_KMATB)     // 55296
#define ATT_SMEM  (ATT_KINI + 512)              // 55808

__global__ __launch_bounds__(256, 1)
void attn_kernel(const int* __restrict__ K_ini)
{
    extern __shared__ char attsm[];
    const uint32_t sb = smem_u32(attsm);
    const int tid  = threadIdx.x;
    const int lane = tid & 31;
    const int w    = tid >> 5;                 // 0..7
    const int qt   = (SS/128 - 1) - blockIdx.x; // longest CTAs first
    const int bh   = blockIdx.y;
    const int b    = bh >> 4;
    const int h    = bh & 15;

    const size_t qkbase = (size_t)bh * SS * DH;   // [bh][s][dh]
    const size_t vtbase = (size_t)bh * DH * SS;   // [bh][dh][s]

    auto load_kv = [&](int kt, int bf) {
        const uint32_t kb = sb + ATT_KV(bf);
        #pragma unroll
        for (int i = 0; i < 2; ++i) {
            const int f = tid + (i << 8);
            const int r = f >> 3, c = f & 7;     // r 0..63
            const uint32_t so = (uint32_t)(r*ATT_ROWB + c*16);
            const size_t gk = qkbase + (size_t)(kt*64 + r)*DH + c*8;
            const size_t gv = vtbase + (size_t)r*SS + kt*64 + c*8;
            cp_async16(kb +             so, g_kh  + gk);
            cp_async16(kb + ATT_KMATB + so, g_vth + gv);
        }
        CP_COMMIT();
    };

    // ---- prologue: Q (128 rows) + K/V tile 0 + kini0
    #pragma unroll
    for (int i = 0; i < 4; ++i) {
        const int f = tid + (i << 8);
        const int r = f >> 3, c = f & 7;         // r 0..127
        const uint32_t so = (uint32_t)(r*ATT_ROWB + c*16);
        const size_t gq = qkbase + (size_t)(qt*128 + r)*DH + c*8;
        cp_async16(sb + so, g_qh + gq);
    }
    load_kv(0, 0);
    if (tid < 16)
        ((int4*)(attsm + ATT_KINI))[tid] = ((const int4*)(K_ini + b*SS))[tid];
    CP_WAIT(0);
    __syncthreads();

    // ---- Q A-fragments (resident)
    uint32_t qf[4][4];
    const uint32_t lrow16 = (uint32_t)((lane & 15) * ATT_ROWB);
    const uint32_t lcol   = (uint32_t)((lane >> 4) << 4);
    #pragma unroll
    for (int kd = 0; kd < 4; ++kd) {
        const uint32_t qa = sb + (uint32_t)(w*16*ATT_ROWB) + lrow16 + kd*32 + lcol;
        ldsm_x4(qf[kd], qa);
    }

    float o[8][4];
    #pragma unroll
    for (int jd = 0; jd < 8; ++jd)
        #pragma unroll
        for (int e = 0; e < 4; ++e) o[jd][e] = 0.f;
    float mrow[2] = {-3.0e38f, -3.0e38f};   // log2-domain running max
    float lrow[2] = {0.f, 0.f};

    const int qr_loc = w*16 + (lane >> 2);     // tile-local row (half0), 0..127
    const int ktmax  = 2*qt + 1;

    for (int kt = 0; kt <= ktmax; ++kt) {
        const int buf = kt & 1;
        if (kt < ktmax) { load_kv(kt + 1, buf ^ 1); CP_WAIT(1); }
        else            { CP_WAIT(0); }
        __syncthreads();
        if (kt < ktmax && tid < 16)
            ((int4*)(attsm + ATT_KINI))[(buf ^ 1)*16 + tid] =
                ((const int4*)(K_ini + b*SS + (kt + 1)*64))[tid];

        // ---- scores S = Q.K^T (1-pass fp16)
        float s[8][4];
        #pragma unroll
        for (int jn = 0; jn < 8; ++jn)
            #pragma unroll
            for (int e = 0; e < 4; ++e) s[jn][e] = 0.f;

        const uint32_t kb = sb + ATT_KV(buf);
        #pragma unroll
        for (int nk = 0; nk < 4; ++nk) {
            #pragma unroll
            for (int kd = 0; kd < 4; ++kd) {
                uint32_t kf[4];
                const uint32_t ad = kb + (uint32_t)(nk*16*ATT_ROWB) + lrow16
                                  + kd*32 + lcol;
                ldsm_x4(kf, ad);
                mma16816(s[nk*2+0], qf[kd], kf[0], kf[2]);
                mma16816(s[nk*2+1], qf[kd], kf[1], kf[3]);
            }
        }

        // ---- scale to log2 domain, mask, tile max
        const int* kini = (const int*)(attsm + ATT_KINI) + buf*64;
        const int needc = (kt >= 2*qt);
        float tmax[2] = {-3.0e38f, -3.0e38f};
        #pragma unroll
        for (int jn = 0; jn < 8; ++jn) {
            #pragma unroll
            for (int e = 0; e < 4; ++e) {
                const int col  = jn*8 + ((lane & 3) << 1) + (e & 1);
                const int half = e >> 1;
                bool masked = (kini[col] == 0);
                if (needc) masked = masked || (kt*64 + col > qt*128 + qr_loc + half*8);
                float sv = s[jn][e] * (0.125f * LOG2E);
                if (masked) sv -= NEG_BIG2;      // exact -1.4427e10 (absorb)
                s[jn][e] = sv;
                tmax[half] = fmaxf(tmax[half], sv);
            }
        }
        #pragma unroll
        for (int half = 0; half < 2; ++half) {
            tmax[half] = fmaxf(tmax[half], __shfl_xor_sync(0xffffffffu, tmax[half], 1));
            tmax[half] = fmaxf(tmax[half], __shfl_xor_sync(0xffffffffu, tmax[half], 2));
        }
        const float nm0 = fmaxf(mrow[0], tmax[0]);
        const float nm1 = fmaxf(mrow[1], tmax[1]);
        const float sc0 = ex2(mrow[0] - nm0);
        const float sc1 = ex2(mrow[1] - nm1);
        mrow[0] = nm0; mrow[1] = nm1;

        // ---- exp2 + P into A-frags (register-only, single fp16)
        uint32_t ap[4][4];
        float ls0 = 0.f, ls1 = 0.f;
        #pragma unroll
        for (int jn = 0; jn < 8; ++jn) {
            const float p0 = ex2(s[jn][0] - nm0);
            const float p1 = ex2(s[jn][1] - nm0);
            const float p2 = ex2(s[jn][2] - nm1);
            const float p3 = ex2(s[jn][3] - nm1);
            ls0 += p0 + p1; ls1 += p2 + p3;
            const int kp  = jn >> 1;
            const int sub = (jn & 1) << 1;
            ap[kp][sub+0] = pk2(__float2half_rn(p0), __float2half_rn(p1));
            ap[kp][sub+1] = pk2(__float2half_rn(p2), __float2half_rn(p3));
        }
        ls0 += __shfl_xor_sync(0xffffffffu, ls0, 1);
        ls0 += __shfl_xor_sync(0xffffffffu, ls0, 2);
        ls1 += __shfl_xor_sync(0xffffffffu, ls1, 1);
        ls1 += __shfl_xor_sync(0xffffffffu, ls1, 2);
        lrow[0] = lrow[0]*sc0 + ls0;
        lrow[1] = lrow[1]*sc1 + ls1;
        #pragma unroll
        for (int jd = 0; jd < 8; ++jd) {
            o[jd][0] *= sc0; o[jd][1] *= sc0;
            o[jd][2] *= sc1; o[jd][3] *= sc1;
        }

        // ---- O += P.V (1-pass fp16)
        const uint32_t vb = kb + ATT_KMATB;
        #pragma unroll
        for (int nd = 0; nd < 4; ++nd) {
            #pragma unroll
            for (int kp = 0; kp < 4; ++kp) {
                uint32_t vf[4];
                const uint32_t ad = vb + (uint32_t)(nd*16*ATT_ROWB) + lrow16
                                  + kp*32 + lcol;
                ldsm_x4(vf, ad);
                mma16816(o[nd*2+0], ap[kp], vf[0], vf[2]);
                mma16816(o[nd*2+1], ap[kp], vf[1], vf[3]);
            }
        }
        __syncthreads();   // protect buf reuse by next iteration's prefetch
    }

    // ---- epilogue: ctx fp16 into the WO-GEMM input (slot 0)
    #pragma unroll
    for (int half = 0; half < 2; ++half) {
        const int row = qr_loc + half*8;
        const size_t mg = (size_t)(b*SS + qt*128 + row);
        const float inv = 1.0f / lrow[half];
        const bool fullmask = (mrow[half] < -1e9f);
        #pragma unroll
        for (int jd = 0; jd < 8; ++jd) {
            const int d = jd*8 + ((lane & 3) << 1);
            float v0, v1;
            if (fullmask) {
                // reference: all scores exactly -1e10 -> uniform softmax over
                // ALL 2048 keys -> mean of V
                v0 = g_vmean[bh*64 + d];
                v1 = g_vmean[bh*64 + d + 1];
            } else {
                v0 = o[jd][half*2+0] * inv;
                v1 = o[jd][half*2+1] * inv;
            }
            const size_t oi = mg*DM + h*64 + d;
            *(__half2*)&g_x[0][oi] =
                __half2(__float2half_rn(v0), __float2half_rn(v1));
        }
    }
}

// ============================ launch ======================================
extern "C" void kernel_launch(void* const* d_in, const int* in_sizes, int n_in,
                              void* d_out, int out_size)
{
    const float* Q_emb = (const float*)d_in[0];
    const float* K_emb = (const float*)d_in[1];
    const float* V_emb = (const float*)d_in[2];
    const int*   K_ini = (const int*)  d_in[4];
    const float* WQ    = (const float*)d_in[5];
    const float* WK    = (const float*)d_in[6];
    const float* WV    = (const float*)d_in[7];
    const float* WO    = (const float*)d_in[8];
    float* out = (float*)d_out;
    (void)in_sizes; (void)n_in; (void)out_size;

    cudaFuncSetAttribute(mma_gemm_kernel,
                         cudaFuncAttributeMaxDynamicSharedMemorySize, GEMM_SMEM);
    cudaFuncSetAttribute(attn_kernel,
                         cudaFuncAttributeMaxDynamicSharedMemorySize, ATT_SMEM);

    // fused conversions (one launch each)
    conv_w_kernel<<<dim3((DM*256)/256, 4), 256>>>(WQ, WK, WV, WO);
    conv_x_kernel<<<dim3((MM*DM/4)/256, 3), 256>>>(Q_emb, K_emb, V_emb);

    // fused QKV projections: grid.z = 3 -> (X_z, W_z, dst_z)
    mma_gemm_kernel<<<dim3(DM/128, MM/128, 3), 256, GEMM_SMEM>>>(nullptr, 0, 0, 0);

    vt_split_kernel<<<dim3(SS/64, BB*HH), 256>>>();   // -> V^T fp16
    vmean_kernel<<<BB*HH, 512>>>();

    attn_kernel<<<dim3(SS/128, BB*HH), 256, ATT_SMEM>>>(K_ini); // -> ctx fp16

    // output projection: ctx (slot 0) @ WO -> out
    mma_gemm_kernel<<<dim3(DM/128, MM/128, 1), 256, GEMM_SMEM>>>(out, 0, 3, 3);
}